// round 1
// baseline (speedup 1.0000x reference)
#include <cuda_runtime.h>
#include <cuda_bf16.h>
#include <math.h>

// Problem shape
#define BB 4
#define TT 2048
#define DD 1024
#define HH 16
#define PP 64
#define FFD 4096
#define ROWS (BB*TT)          // 8192

// ---------------- scratch (device globals; no allocation allowed) -------------
__device__ float g_nX [ROWS*DD];
__device__ float g_Q  [ROWS*DD];
__device__ float g_K  [ROWS*DD];
__device__ float g_V  [ROWS*DD];
__device__ float g_NV [ROWS*DD];
__device__ float g_SS [ROWS*DD];
__device__ float g_PRE[ROWS*DD];
__device__ float g_HID[ROWS*FFD];

__device__ __forceinline__ float gelu_f(float x) {
    return 0.5f * x * (1.0f + erff(x * 0.70710678118654752440f));
}

// ---------------- LayerNorm (optionally + residual added AFTER LN) ------------
// Y[row] = (res ? res[row] : 0) + LN(X[row]) * g + b
__global__ void ln_kernel(const float* __restrict__ X, const float* __restrict__ gg,
                          const float* __restrict__ bb, float* __restrict__ Y,
                          const float* __restrict__ res)
{
    __shared__ float s1[256], s2[256];
    const int row = blockIdx.x;
    const int t = threadIdx.x;
    const float4* xr = (const float4*)(X + (size_t)row * DD);
    float4 v = xr[t];
    float s = v.x + v.y + v.z + v.w;
    float q = v.x*v.x + v.y*v.y + v.z*v.z + v.w*v.w;
    s1[t] = s; s2[t] = q;
    __syncthreads();
    #pragma unroll
    for (int o = 128; o > 0; o >>= 1) {
        if (t < o) { s1[t] += s1[t+o]; s2[t] += s2[t+o]; }
        __syncthreads();
    }
    const float mu  = s1[0] * (1.0f/1024.0f);
    const float var = s2[0] * (1.0f/1024.0f) - mu*mu;
    const float inv = rsqrtf(var + 1e-5f);
    float4 g4 = ((const float4*)gg)[t];
    float4 b4 = ((const float4*)bb)[t];
    float4 o;
    o.x = (v.x-mu)*inv*g4.x + b4.x;
    o.y = (v.y-mu)*inv*g4.y + b4.y;
    o.z = (v.z-mu)*inv*g4.z + b4.z;
    o.w = (v.w-mu)*inv*g4.w + b4.w;
    if (res) {
        float4 r = ((const float4*)(res + (size_t)row * DD))[t];
        o.x += r.x; o.y += r.y; o.z += r.z; o.w += r.w;
    }
    ((float4*)(Y + (size_t)row * DD))[t] = o;
}

// ---------------- generic tiled SGEMM: C = act(A@B + bias) + residual --------
// A: [M,K] row-major. bLayout: 0 -> B row-major [K,N];
//                              1 -> B is [H, K, 64] (col = h*64+p)  (WQ/WK/WV layout)
__global__ void gemm64x64(const float* __restrict__ A, const float* __restrict__ B,
                          float* __restrict__ C, int M, int N, int K, int bLayout,
                          const float* __restrict__ bias,
                          const float* __restrict__ residual, int act)
{
    __shared__ float As[16][68];
    __shared__ float Bs[16][64];
    const int tx = threadIdx.x, ty = threadIdx.y;
    const int tid = ty * 16 + tx;
    const int row0 = blockIdx.y * 64;
    const int col0 = blockIdx.x * 64;
    float acc[4][4] = {};

    for (int k0 = 0; k0 < K; k0 += 16) {
        #pragma unroll
        for (int i = 0; i < 4; i++) {
            int idx = tid + i * 256;
            int m = idx >> 4, kk = idx & 15;
            As[kk][m] = A[(size_t)(row0 + m) * K + k0 + kk];
        }
        #pragma unroll
        for (int i = 0; i < 4; i++) {
            int idx = tid + i * 256;
            int kk = idx >> 6, n = idx & 63;
            int col = col0 + n;
            float v;
            if (bLayout == 0) v = B[(size_t)(k0 + kk) * N + col];
            else              v = B[(size_t)(col >> 6) * K * 64 + (size_t)(k0 + kk) * 64 + (col & 63)];
            Bs[kk][n] = v;
        }
        __syncthreads();
        #pragma unroll
        for (int kk = 0; kk < 16; kk++) {
            float4 a4 = *(const float4*)&As[kk][ty * 4];
            float4 b4 = *(const float4*)&Bs[kk][tx * 4];
            float a[4] = {a4.x, a4.y, a4.z, a4.w};
            float b[4] = {b4.x, b4.y, b4.z, b4.w};
            #pragma unroll
            for (int i = 0; i < 4; i++)
                #pragma unroll
                for (int j = 0; j < 4; j++)
                    acc[i][j] += a[i] * b[j];
        }
        __syncthreads();
    }
    #pragma unroll
    for (int i = 0; i < 4; i++) {
        int row = row0 + ty * 4 + i;
        #pragma unroll
        for (int j = 0; j < 4; j++) {
            int col = col0 + tx * 4 + j;
            float v = acc[i][j];
            if (bias)     v += bias[col];
            if (act)      v  = gelu_f(v);
            if (residual) v += residual[(size_t)row * N + col];
            C[(size_t)row * N + col] = v;
        }
    }
}

// ---------------- scores: S[b,h,q,k] = (K[b,q,h,:] . Q[b,k,h,:]) / sqrt(P) ----
// NOTE: reference swaps q/k (queries carry index k).
__global__ void scores_kernel(const float* __restrict__ Kmat, const float* __restrict__ Qmat,
                              float* __restrict__ S)
{
    const int bh = blockIdx.z;
    const int b = bh >> 4, h = bh & 15;
    const int q0 = blockIdx.y * 64;
    const int kc0 = blockIdx.x * 64;
    const int tx = threadIdx.x, ty = threadIdx.y;
    const int tid = ty * 16 + tx;
    __shared__ float As[16][68];
    __shared__ float Bs[16][68];
    float acc[4][4] = {};
    const float* Kh = Kmat + (size_t)b * TT * DD + h * PP;
    const float* Qh = Qmat + (size_t)b * TT * DD + h * PP;

    #pragma unroll
    for (int p0 = 0; p0 < PP; p0 += 16) {
        #pragma unroll
        for (int i = 0; i < 4; i++) {
            int idx = tid + i * 256;
            int m = idx >> 4, kk = idx & 15;
            As[kk][m] = Kh[(size_t)(q0 + m) * DD + p0 + kk];
        }
        #pragma unroll
        for (int i = 0; i < 4; i++) {
            int idx = tid + i * 256;
            int m = idx >> 4, kk = idx & 15;
            Bs[kk][m] = Qh[(size_t)(kc0 + m) * DD + p0 + kk];
        }
        __syncthreads();
        #pragma unroll
        for (int kk = 0; kk < 16; kk++) {
            float4 a4 = *(const float4*)&As[kk][ty * 4];
            float4 b4 = *(const float4*)&Bs[kk][tx * 4];
            float a[4] = {a4.x, a4.y, a4.z, a4.w};
            float bv[4] = {b4.x, b4.y, b4.z, b4.w};
            #pragma unroll
            for (int i = 0; i < 4; i++)
                #pragma unroll
                for (int j = 0; j < 4; j++)
                    acc[i][j] += a[i] * bv[j];
        }
        __syncthreads();
    }
    #pragma unroll
    for (int i = 0; i < 4; i++) {
        int q = q0 + ty * 4 + i;
        #pragma unroll
        for (int j = 0; j < 4; j++) {
            int k = kc0 + tx * 4 + j;
            S[((size_t)bh * TT + q) * TT + k] = acc[i][j] * 0.125f;  // 1/sqrt(64)
        }
    }
}

// ---------------- in-place row softmax over last axis (row length 2048) ------
__global__ void softmax_kernel(float* __restrict__ S)
{
    __shared__ float red[256];
    const size_t row = blockIdx.x;
    float* p = S + row * (size_t)TT;
    const int t = threadIdx.x;
    float v[8];
    float mx = -1e30f;
    #pragma unroll
    for (int i = 0; i < 8; i++) { v[i] = p[t + i * 256]; mx = fmaxf(mx, v[i]); }
    red[t] = mx; __syncthreads();
    #pragma unroll
    for (int o = 128; o > 0; o >>= 1) {
        if (t < o) red[t] = fmaxf(red[t], red[t+o]);
        __syncthreads();
    }
    mx = red[0];
    __syncthreads();
    float sum = 0.0f;
    #pragma unroll
    for (int i = 0; i < 8; i++) { v[i] = __expf(v[i] - mx); sum += v[i]; }
    red[t] = sum; __syncthreads();
    #pragma unroll
    for (int o = 128; o > 0; o >>= 1) {
        if (t < o) red[t] += red[t+o];
        __syncthreads();
    }
    const float inv = 1.0f / red[0];
    #pragma unroll
    for (int i = 0; i < 8; i++) p[t + i * 256] = v[i] * inv;
}

// ---------------- NV[b,q,h,p] = sum_k attn[b,h,q,k] * V[b,k,h,p] --------------
__global__ void av_kernel(const float* __restrict__ Attn, const float* __restrict__ Vmat,
                          float* __restrict__ NV)
{
    const int bh = blockIdx.y;
    const int b = bh >> 4, h = bh & 15;
    const int q0 = blockIdx.x * 64;
    const int tx = threadIdx.x, ty = threadIdx.y;
    const int tid = ty * 16 + tx;
    __shared__ float As[16][68];
    __shared__ float Bs[16][64];
    float acc[4][4] = {};
    const float* Ah = Attn + (size_t)bh * TT * TT;
    const float* Vh = Vmat + (size_t)b * TT * DD + h * PP;

    for (int k0 = 0; k0 < TT; k0 += 16) {
        #pragma unroll
        for (int i = 0; i < 4; i++) {
            int idx = tid + i * 256;
            int m = idx >> 4, kk = idx & 15;
            As[kk][m] = Ah[(size_t)(q0 + m) * TT + k0 + kk];
        }
        #pragma unroll
        for (int i = 0; i < 4; i++) {
            int idx = tid + i * 256;
            int kk = idx >> 6, n = idx & 63;
            Bs[kk][n] = Vh[(size_t)(k0 + kk) * DD + n];
        }
        __syncthreads();
        #pragma unroll
        for (int kk = 0; kk < 16; kk++) {
            float4 a4 = *(const float4*)&As[kk][ty * 4];
            float4 b4 = *(const float4*)&Bs[kk][tx * 4];
            float a[4] = {a4.x, a4.y, a4.z, a4.w};
            float bv[4] = {b4.x, b4.y, b4.z, b4.w};
            #pragma unroll
            for (int i = 0; i < 4; i++)
                #pragma unroll
                for (int j = 0; j < 4; j++)
                    acc[i][j] += a[i] * bv[j];
        }
        __syncthreads();
    }
    #pragma unroll
    for (int i = 0; i < 4; i++) {
        int q = q0 + ty * 4 + i;
        #pragma unroll
        for (int j = 0; j < 4; j++) {
            int pcol = tx * 4 + j;
            NV[(size_t)(b * TT + q) * DD + h * PP + pcol] = acc[i][j];
        }
    }
}

// -----------------------------------------------------------------------------
extern "C" void kernel_launch(void* const* d_in, const int* in_sizes, int n_in,
                              void* d_out, int out_size)
{
    const float* X      = (const float*)d_in[0];
    const float* WQ     = (const float*)d_in[1];
    const float* WK     = (const float*)d_in[2];
    const float* WV     = (const float*)d_in[3];
    const float* WO     = (const float*)d_in[4];
    const float* attn_g = (const float*)d_in[5];
    const float* attn_b = (const float*)d_in[6];
    const float* ff_g   = (const float*)d_in[7];
    const float* ff_b   = (const float*)d_in[8];
    const float* fW1    = (const float*)d_in[9];
    const float* fb1    = (const float*)d_in[10];
    const float* fW2    = (const float*)d_in[11];
    const float* fb2    = (const float*)d_in[12];

    float* out1 = (float*)d_out;                               // [B,T,D]
    float* attn = (float*)d_out + (size_t)BB * TT * DD;        // [B,H,T,T]

    float *nX, *Q, *K_, *V, *NV, *SS, *PRE, *HID;
    cudaGetSymbolAddress((void**)&nX,  g_nX);
    cudaGetSymbolAddress((void**)&Q,   g_Q);
    cudaGetSymbolAddress((void**)&K_,  g_K);
    cudaGetSymbolAddress((void**)&V,   g_V);
    cudaGetSymbolAddress((void**)&NV,  g_NV);
    cudaGetSymbolAddress((void**)&SS,  g_SS);
    cudaGetSymbolAddress((void**)&PRE, g_PRE);
    cudaGetSymbolAddress((void**)&HID, g_HID);

    dim3 blk(16, 16);

    // 1. nX = LN(X)
    ln_kernel<<<ROWS, 256>>>(X, attn_g, attn_b, nX, nullptr);

    // 2-4. Q/K/V = nX @ W{Q,K,V}   (weights in [H,D,P] layout -> bLayout=1)
    gemm64x64<<<dim3(DD/64, ROWS/64), blk>>>(nX, WQ, Q,  ROWS, DD, DD, 1, nullptr, nullptr, 0);
    gemm64x64<<<dim3(DD/64, ROWS/64), blk>>>(nX, WK, K_, ROWS, DD, DD, 1, nullptr, nullptr, 0);
    gemm64x64<<<dim3(DD/64, ROWS/64), blk>>>(nX, WV, V,  ROWS, DD, DD, 1, nullptr, nullptr, 0);

    // 5. scores -> attn region of d_out (raw), then 6. softmax in place
    scores_kernel<<<dim3(TT/64, TT/64, BB*HH), blk>>>(K_, Q, attn);
    softmax_kernel<<<BB*HH*TT, 256>>>(attn);

    // 7. new_values = attn @ V
    av_kernel<<<dim3(TT/64, BB*HH), blk>>>(attn, V, NV);

    // 8. seq_summary = NV @ WO   (WO is [H,P,D] == row-major [1024,1024])
    gemm64x64<<<dim3(DD/64, ROWS/64), blk>>>(NV, WO, SS, ROWS, DD, DD, 0, nullptr, nullptr, 0);

    // 9. pre_ff = X + LN(seq_summary)
    ln_kernel<<<ROWS, 256>>>(SS, ff_g, ff_b, PRE, X);

    // 10. hidden = gelu(pre_ff @ fW1 + fb1)
    gemm64x64<<<dim3(FFD/64, ROWS/64), blk>>>(PRE, fW1, HID, ROWS, FFD, DD, 0, fb1, nullptr, 1);

    // 11. out1 = hidden @ fW2 + fb2 + pre_ff
    gemm64x64<<<dim3(DD/64, ROWS/64), blk>>>(HID, fW2, out1, ROWS, DD, FFD, 0, fb2, PRE, 0);
}